// round 17
// baseline (speedup 1.0000x reference)
#include <cuda_runtime.h>
#include <cuda_bf16.h>
#include <math.h>

#define N_NODES   100000
#define N_EDGES   800000
#define NODE_IN   32
#define EDGE_DIM  84
#define HIDDEN    24
#define HEAD_HIDDEN 20
#define DEPTH     2
#define LN_EPS    1e-5f

#define TE 256            // edges per block
#define ETHREADS 1024
#define ES_S (TE + 1)     // 257: stride ≡ 1 mod 32 -> conflict-free everywhere

typedef unsigned long long ull;

// ---------------- packed f32x2 helpers (Blackwell FFMA2) ----------------
__device__ __forceinline__ ull pk(float lo, float hi) {
    ull r; asm("mov.b64 %0, {%1,%2};" : "=l"(r) : "f"(lo), "f"(hi)); return r;
}
__device__ __forceinline__ void upk(ull v, float& lo, float& hi) {
    asm("mov.b64 {%0,%1}, %2;" : "=f"(lo), "=f"(hi) : "l"(v));
}
__device__ __forceinline__ ull fma2(ull a, ull b, ull c) {
    ull d; asm("fma.rn.f32x2 %0, %1, %2, %3;" : "=l"(d) : "l"(a), "l"(b), "l"(c)); return d;
}
__device__ __forceinline__ float gelu(float x) {
    return 0.5f * x * (1.0f + erff(x * 0.7071067811865476f));
}

// ---------------- scratch (device globals: allocation-free) ----------------
__device__ float g_h[N_NODES * HIDDEN];
__device__ float g_intr[N_NODES];
__device__ float g_cnt[N_NODES];
__device__ float g_Ps[N_NODES * EDGE_DIM];
__device__ float g_Pd[N_NODES * EDGE_DIM];
__device__ float g_Qs[N_NODES * HIDDEN];
__device__ float g_Qd[N_NODES * HIDDEN];
__device__ float g_agg[N_NODES * HIDDEN];
__device__ float g_e[(size_t)N_EDGES * EDGE_DIM];

// ---------------- edge-count kernel ----------------
__global__ void k_count(const int* __restrict__ dst) {
    int e = blockIdx.x * blockDim.x + threadIdx.x;
    if (e < N_EDGES) atomicAdd(&g_cnt[dst[e]], 1.0f);
}

// ---------------- input projection + intrinsic head (+ cnt zeroing) ----------------
__global__ void __launch_bounds__(256) k_input(
    const float* __restrict__ x, const float* __restrict__ node_w,
    const float* __restrict__ node_b, const float* __restrict__ ih_w1,
    const float* __restrict__ ih_b1, const float* __restrict__ ih_w2,
    const float* __restrict__ ih_b2)
{
    __shared__ float sw[NODE_IN * HIDDEN];
    __shared__ float sbias[HIDDEN];
    __shared__ float sw1[HIDDEN * HEAD_HIDDEN];
    __shared__ float sb1h[HEAD_HIDDEN];
    __shared__ float sw2[HEAD_HIDDEN];
    __shared__ float sb2h;
    int tid = threadIdx.x;
    for (int i = tid; i < NODE_IN * HIDDEN; i += 256) sw[i] = node_w[i];
    for (int i = tid; i < HIDDEN * HEAD_HIDDEN; i += 256) sw1[i] = ih_w1[i];
    if (tid < HIDDEN) sbias[tid] = node_b[tid];
    if (tid < HEAD_HIDDEN) { sb1h[tid] = ih_b1[tid]; sw2[tid] = ih_w2[tid]; }
    if (tid == 0) sb2h = ih_b2[0];
    __syncthreads();
    int n = blockIdx.x * 256 + tid;
    if (n >= N_NODES) return;
    g_cnt[n] = 0.0f;

    float xr[NODE_IN];
    #pragma unroll
    for (int k = 0; k < NODE_IN; k += 4) {
        float4 v = *(const float4*)(x + (size_t)n * NODE_IN + k);
        xr[k] = v.x; xr[k+1] = v.y; xr[k+2] = v.z; xr[k+3] = v.w;
    }
    ull acc[HIDDEN / 2];
    #pragma unroll
    for (int j = 0; j < HIDDEN / 2; j++) acc[j] = pk(sbias[2*j], sbias[2*j+1]);
    #pragma unroll 4
    for (int k = 0; k < NODE_IN; k++) {
        ull xv = pk(xr[k], xr[k]);
        const ulonglong2* wr = (const ulonglong2*)(sw + k * HIDDEN);
        ulonglong2 w0 = wr[0], w1 = wr[1], w2 = wr[2], w3 = wr[3], w4 = wr[4], w5 = wr[5];
        acc[0]=fma2(xv,w0.x,acc[0]);  acc[1]=fma2(xv,w0.y,acc[1]);
        acc[2]=fma2(xv,w1.x,acc[2]);  acc[3]=fma2(xv,w1.y,acc[3]);
        acc[4]=fma2(xv,w2.x,acc[4]);  acc[5]=fma2(xv,w2.y,acc[5]);
        acc[6]=fma2(xv,w3.x,acc[6]);  acc[7]=fma2(xv,w3.y,acc[7]);
        acc[8]=fma2(xv,w4.x,acc[8]);  acc[9]=fma2(xv,w4.y,acc[9]);
        acc[10]=fma2(xv,w5.x,acc[10]); acc[11]=fma2(xv,w5.y,acc[11]);
    }
    float h[HIDDEN];
    #pragma unroll
    for (int j = 0; j < HIDDEN / 2; j++) upk(acc[j], h[2*j], h[2*j+1]);
    #pragma unroll
    for (int k = 0; k < HIDDEN; k += 4)
        *(float4*)(g_h + (size_t)n * HIDDEN + k) = make_float4(h[k], h[k+1], h[k+2], h[k+3]);

    ull t[HEAD_HIDDEN / 2];
    #pragma unroll
    for (int j = 0; j < HEAD_HIDDEN / 2; j++) t[j] = pk(sb1h[2*j], sb1h[2*j+1]);
    #pragma unroll 4
    for (int k = 0; k < HIDDEN; k++) {
        ull hv = pk(h[k], h[k]);
        const ull* wr = (const ull*)(sw1 + k * HEAD_HIDDEN);
        #pragma unroll
        for (int j = 0; j < HEAD_HIDDEN / 2; j++) t[j] = fma2(hv, wr[j], t[j]);
    }
    float r = sb2h;
    #pragma unroll
    for (int j = 0; j < HEAD_HIDDEN / 2; j++) {
        float lo, hi; upk(t[j], lo, hi);
        r += gelu(lo) * sw2[2*j] + gelu(hi) * sw2[2*j+1];
    }
    g_intr[n] = r;
}

// ---------------- per-layer node-side projections (+ agg zeroing) ----------------
__global__ void __launch_bounds__(256) k_nodeproj(
    const float* __restrict__ pe_w1_l, const float* __restrict__ pv_w1_l)
{
    __shared__ float we[48 * 88];
    __shared__ float wv[48 * HIDDEN];
    int tid = threadIdx.x;
    for (int i = tid; i < 48 * EDGE_DIM; i += 256) {
        int k = i / EDGE_DIM, c = i - k * EDGE_DIM;
        we[k * 88 + c] = pe_w1_l[i];
    }
    for (int i = tid; i < 48 * HIDDEN; i += 256) wv[i] = pv_w1_l[i];
    __syncthreads();
    int n = blockIdx.x * 256 + tid;
    if (n >= N_NODES) return;

    float4 z = make_float4(0.f, 0.f, 0.f, 0.f);
    #pragma unroll
    for (int k = 0; k < HIDDEN; k += 4) *(float4*)(g_agg + (size_t)n * HIDDEN + k) = z;

    ull h2[HIDDEN];
    #pragma unroll
    for (int k = 0; k < HIDDEN; k += 4) {
        float4 v = *(const float4*)(g_h + (size_t)n * HIDDEN + k);
        h2[k] = pk(v.x, v.x); h2[k+1] = pk(v.y, v.y);
        h2[k+2] = pk(v.z, v.z); h2[k+3] = pk(v.w, v.w);
    }
    #pragma unroll 1
    for (int ch = 0; ch < 7; ch++) {
        int c0 = ch * 12;
        ull as[6], ad[6];
        #pragma unroll
        for (int j = 0; j < 6; j++) { as[j] = 0ULL; ad[j] = 0ULL; }
        #pragma unroll 4
        for (int k = 0; k < 24; k++) {
            const ulonglong2* ws = (const ulonglong2*)(we + k * 88 + c0);
            const ulonglong2* wd = (const ulonglong2*)(we + (k + 24) * 88 + c0);
            ulonglong2 s0 = ws[0], s1 = ws[1], s2 = ws[2];
            ulonglong2 d0 = wd[0], d1 = wd[1], d2 = wd[2];
            ull hk = h2[k];
            as[0]=fma2(hk,s0.x,as[0]); as[1]=fma2(hk,s0.y,as[1]);
            as[2]=fma2(hk,s1.x,as[2]); as[3]=fma2(hk,s1.y,as[3]);
            as[4]=fma2(hk,s2.x,as[4]); as[5]=fma2(hk,s2.y,as[5]);
            ad[0]=fma2(hk,d0.x,ad[0]); ad[1]=fma2(hk,d0.y,ad[1]);
            ad[2]=fma2(hk,d1.x,ad[2]); ad[3]=fma2(hk,d1.y,ad[3]);
            ad[4]=fma2(hk,d2.x,ad[4]); ad[5]=fma2(hk,d2.y,ad[5]);
        }
        float o[12];
        #pragma unroll
        for (int j = 0; j < 6; j++) upk(as[j], o[2*j], o[2*j+1]);
        #pragma unroll
        for (int k = 0; k < 12; k += 4)
            *(float4*)(g_Ps + (size_t)n * EDGE_DIM + c0 + k) = make_float4(o[k], o[k+1], o[k+2], o[k+3]);
        #pragma unroll
        for (int j = 0; j < 6; j++) upk(ad[j], o[2*j], o[2*j+1]);
        #pragma unroll
        for (int k = 0; k < 12; k += 4)
            *(float4*)(g_Pd + (size_t)n * EDGE_DIM + c0 + k) = make_float4(o[k], o[k+1], o[k+2], o[k+3]);
    }
    #pragma unroll 1
    for (int ch = 0; ch < 2; ch++) {
        int c0 = ch * 12;
        ull as[6], ad[6];
        #pragma unroll
        for (int j = 0; j < 6; j++) { as[j] = 0ULL; ad[j] = 0ULL; }
        #pragma unroll 4
        for (int k = 0; k < 24; k++) {
            const ulonglong2* ws = (const ulonglong2*)(wv + k * HIDDEN + c0);
            const ulonglong2* wd = (const ulonglong2*)(wv + (k + 24) * HIDDEN + c0);
            ulonglong2 s0 = ws[0], s1 = ws[1], s2 = ws[2];
            ulonglong2 d0 = wd[0], d1 = wd[1], d2 = wd[2];
            ull hk = h2[k];
            as[0]=fma2(hk,s0.x,as[0]); as[1]=fma2(hk,s0.y,as[1]);
            as[2]=fma2(hk,s1.x,as[2]); as[3]=fma2(hk,s1.y,as[3]);
            as[4]=fma2(hk,s2.x,as[4]); as[5]=fma2(hk,s2.y,as[5]);
            ad[0]=fma2(hk,d0.x,ad[0]); ad[1]=fma2(hk,d0.y,ad[1]);
            ad[2]=fma2(hk,d1.x,ad[2]); ad[3]=fma2(hk,d1.y,ad[3]);
            ad[4]=fma2(hk,d2.x,ad[4]); ad[5]=fma2(hk,d2.y,ad[5]);
        }
        float o[12];
        #pragma unroll
        for (int j = 0; j < 6; j++) upk(as[j], o[2*j], o[2*j+1]);
        #pragma unroll
        for (int k = 0; k < 12; k += 4)
            *(float4*)(g_Qs + (size_t)n * HIDDEN + c0 + k) = make_float4(o[k], o[k+1], o[k+2], o[k+3]);
        #pragma unroll
        for (int j = 0; j < 6; j++) upk(ad[j], o[2*j], o[2*j+1]);
        #pragma unroll
        for (int k = 0; k < 12; k += 4)
            *(float4*)(g_Qd + (size_t)n * HIDDEN + c0 + k) = make_float4(o[k], o[k+1], o[k+2], o[k+3]);
    }
}

// ---------------- fused per-layer edge kernel (1024 threads; 28 GEMM warps) ----------------
// SMEM (floats): es[84][257] + us[84][257] + sW[84][84] + sWv1[84][24] + sWv2[24][24]
//                + biases(384) + pad(24) + sidx(256) + didx(256) = 53744 floats = 215.0 KB
#define EDGE_SMEM_FLOATS (2 * EDGE_DIM * ES_S + EDGE_DIM * EDGE_DIM + EDGE_DIM * HIDDEN + HIDDEN * HIDDEN + 384 + 24 + 2 * TE)
#define EDGE_SMEM_BYTES  (EDGE_SMEM_FLOATS * 4)

__global__ void __launch_bounds__(ETHREADS, 1) k_edge(
    const float* __restrict__ ein_p,
    const int* __restrict__ src, const int* __restrict__ dst,
    const float* __restrict__ we1,  const float* __restrict__ pb1,
    const float* __restrict__ we2,  const float* __restrict__ pb2,
    const float* __restrict__ neg,  const float* __restrict__ neb,
    const float* __restrict__ wv1,  const float* __restrict__ vb1,
    const float* __restrict__ wv2,  const float* __restrict__ vb2,
    int store_e)
{
    extern __shared__ float smem[];
    float* es   = smem;
    float* us   = es + EDGE_DIM * ES_S;
    float* sW   = us + EDGE_DIM * ES_S;                 // 84x84, reused We1 -> pe_w2
    float* sWv1 = sW + EDGE_DIM * EDGE_DIM;             // 84x24
    float* sWv2 = sWv1 + EDGE_DIM * HIDDEN;             // 24x24
    float* sb1  = sWv2 + HIDDEN * HIDDEN;               // 84
    float* sb2  = sb1 + EDGE_DIM;                       // 84
    float* sg   = sb2 + EDGE_DIM;                       // 84
    float* sbt  = sg + EDGE_DIM;                        // 84
    float* svb1 = sbt + EDGE_DIM;                       // 24
    float* svb2 = svb1 + HIDDEN;                        // 24 (+24 pad before sidx)
    int*   sidx = (int*)(svb2 + 2 * HIDDEN);            // 256
    int*   didx = sidx + TE;                            // 256

    int tid = threadIdx.x;
    int base = blockIdx.x * TE;
    const float* ein = ein_p ? ein_p : g_e;

    // ---- P1: stage e tile (transposed), weights, params, indices ----
    for (int i = tid; i < EDGE_DIM * TE; i += ETHREADS) {
        int ee = i / EDGE_DIM, k = i - ee * EDGE_DIM;
        es[k * ES_S + ee] = ein[(size_t)(base + ee) * EDGE_DIM + k];
    }
    for (int i = tid; i < EDGE_DIM * EDGE_DIM; i += ETHREADS) sW[i] = we1[i];
    for (int i = tid; i < EDGE_DIM * HIDDEN; i += ETHREADS) sWv1[i] = wv1[i];
    for (int i = tid; i < HIDDEN * HIDDEN; i += ETHREADS) sWv2[i] = wv2[i];
    if (tid < EDGE_DIM) { sb1[tid] = pb1[tid]; sb2[tid] = pb2[tid]; sg[tid] = neg[tid]; sbt[tid] = neb[tid]; }
    if (tid >= 128 && tid < 128 + HIDDEN) { svb1[tid-128] = vb1[tid-128]; svb2[tid-128] = vb2[tid-128]; }
    if (tid >= 256 && tid < 512) { sidx[tid-256] = src[base + tid - 256]; didx[tid-256] = dst[base + tid - 256]; }
    __syncthreads();

    int wid = tid >> 5, lane = tid & 31;

    // ---- P2: u = gelu(Ps[s] + Pd[d] + e @ We1 + b1) ----
    // 28 warps: cg = col group (0..13) -> cols [6cg,6cg+6); eh = edge half.
    // Thread owns 4 edges: eh*128 + lane + 32j. Gathers front-loaded into acc init.
    if (wid < 28) {
        int eh = (wid >= 14) ? 1 : 0;
        int cg = wid - 14 * eh;
        int c0 = cg * 6;
        int e0 = lane + (eh << 7);
        ull acc[4][3];
        #pragma unroll
        for (int j = 0; j < 4; j++) {
            int ee = e0 + 32 * j;
            int s = sidx[ee], d = didx[ee];
            const float* ps = g_Ps + (size_t)s * EDGE_DIM + c0;
            const float* pd = g_Pd + (size_t)d * EDGE_DIM + c0;
            float2 a0 = *(const float2*)(ps);
            float2 a1 = *(const float2*)(ps + 2);
            float2 a2 = *(const float2*)(ps + 4);
            float2 b0 = *(const float2*)(pd);
            float2 b1 = *(const float2*)(pd + 2);
            float2 b2 = *(const float2*)(pd + 4);
            acc[j][0] = pk(a0.x + b0.x + sb1[c0+0], a0.y + b0.y + sb1[c0+1]);
            acc[j][1] = pk(a1.x + b1.x + sb1[c0+2], a1.y + b1.y + sb1[c0+3]);
            acc[j][2] = pk(a2.x + b2.x + sb1[c0+4], a2.y + b2.y + sb1[c0+5]);
        }
        const float* eb = es + e0;
        const float* wb = sW + c0;
        #pragma unroll 2
        for (int k = 0; k < EDGE_DIM; k++) {
            const ull* wr = (const ull*)(wb + k * EDGE_DIM);
            ull w0 = wr[0], w1 = wr[1], w2 = wr[2];
            const float* er = eb + k * ES_S;
            #pragma unroll
            for (int j = 0; j < 4; j++) {
                float ev = er[32 * j];
                ull e2 = pk(ev, ev);
                acc[j][0] = fma2(e2, w0, acc[j][0]);
                acc[j][1] = fma2(e2, w1, acc[j][1]);
                acc[j][2] = fma2(e2, w2, acc[j][2]);
            }
        }
        #pragma unroll
        for (int j = 0; j < 4; j++) {
            float* uc = us + e0 + 32 * j;
            #pragma unroll
            for (int c = 0; c < 3; c++) {
                float lo, hi; upk(acc[j][c], lo, hi);
                uc[(c0 + 2*c)     * ES_S] = gelu(lo);
                uc[(c0 + 2*c + 1) * ES_S] = gelu(hi);
            }
        }
    }
    __syncthreads();

    // ---- P3: reload sW with pe_w2 ----
    for (int i = tid; i < EDGE_DIM * EDGE_DIM; i += ETHREADS) sW[i] = we2[i];
    __syncthreads();

    // ---- P4: r = e + (u @ pe_w2 + b2)  -> es ----
    if (wid < 28) {
        int eh = (wid >= 14) ? 1 : 0;
        int cg = wid - 14 * eh;
        int c0 = cg * 6;
        int e0 = lane + (eh << 7);
        ull acc[4][3];
        #pragma unroll
        for (int j = 0; j < 4; j++) {
            acc[j][0] = pk(sb2[c0+0], sb2[c0+1]);
            acc[j][1] = pk(sb2[c0+2], sb2[c0+3]);
            acc[j][2] = pk(sb2[c0+4], sb2[c0+5]);
        }
        const float* ub = us + e0;
        const float* wb = sW + c0;
        #pragma unroll 2
        for (int k = 0; k < EDGE_DIM; k++) {
            const ull* wr = (const ull*)(wb + k * EDGE_DIM);
            ull w0 = wr[0], w1 = wr[1], w2 = wr[2];
            const float* ur = ub + k * ES_S;
            #pragma unroll
            for (int j = 0; j < 4; j++) {
                float uv = ur[32 * j];
                ull u2 = pk(uv, uv);
                acc[j][0] = fma2(u2, w0, acc[j][0]);
                acc[j][1] = fma2(u2, w1, acc[j][1]);
                acc[j][2] = fma2(u2, w2, acc[j][2]);
            }
        }
        #pragma unroll
        for (int j = 0; j < 4; j++) {
            float* ec = es + e0 + 32 * j;
            #pragma unroll
            for (int c = 0; c < 3; c++) {
                float lo, hi; upk(acc[j][c], lo, hi);
                int ca = c0 + 2*c, cb = ca + 1;
                ec[ca * ES_S] += lo;
                ec[cb * ES_S] += hi;
            }
        }
    }
    __syncthreads();

    // ---- P5: per-edge LayerNorm of es (threads 0..255) ----
    if (tid < TE) {
        float* ec = es + tid;
        float sum = 0.0f, sq = 0.0f;
        #pragma unroll 4
        for (int c = 0; c < EDGE_DIM; c++) {
            float v = ec[c * ES_S];
            sum += v; sq += v * v;
        }
        float mean = sum * (1.0f / EDGE_DIM);
        float var  = fmaxf(sq * (1.0f / EDGE_DIM) - mean * mean, 0.0f);
        float rstd = rsqrtf(var + LN_EPS);
        #pragma unroll 4
        for (int c = 0; c < EDGE_DIM; c++) {
            float v = ec[c * ES_S];
            ec[c * ES_S] = (v - mean) * rstd * sg[c] + sbt[c];
        }
    }
    __syncthreads();

    // ---- P6a: v = gelu(Qs[s] + Qd[d] + e @ Wv1 + b1) -> us rows 0..23 ----
    // 4 groups of 256 threads: group g owns cols [6g,6g+6); thread owns edge tid&255.
    {
        int g = tid >> 8;
        int t = tid & 255;
        int c0 = 6 * g;
        int s = sidx[t], d = didx[t];
        const float* qs = g_Qs + (size_t)s * HIDDEN + c0;
        const float* qd = g_Qd + (size_t)d * HIDDEN + c0;
        float2 a0 = *(const float2*)(qs);
        float2 a1 = *(const float2*)(qs + 2);
        float2 a2 = *(const float2*)(qs + 4);
        float2 b0 = *(const float2*)(qd);
        float2 b1 = *(const float2*)(qd + 2);
        float2 b2 = *(const float2*)(qd + 4);
        ull acc0 = pk(a0.x + b0.x + svb1[c0+0], a0.y + b0.y + svb1[c0+1]);
        ull acc1 = pk(a1.x + b1.x + svb1[c0+2], a1.y + b1.y + svb1[c0+3]);
        ull acc2 = pk(a2.x + b2.x + svb1[c0+4], a2.y + b2.y + svb1[c0+5]);
        const float* eb = es + t;
        const float* wb = sWv1 + c0;
        #pragma unroll 2
        for (int k = 0; k < EDGE_DIM; k++) {
            const ull* wr = (const ull*)(wb + k * HIDDEN);
            ull w0 = wr[0], w1 = wr[1], w2 = wr[2];
            float ev = eb[k * ES_S];
            ull e2 = pk(ev, ev);
            acc0 = fma2(e2, w0, acc0);
            acc1 = fma2(e2, w1, acc1);
            acc2 = fma2(e2, w2, acc2);
        }
        float* uc = us + t;
        float lo, hi;
        upk(acc0, lo, hi); uc[(c0+0)*ES_S] = gelu(lo); uc[(c0+1)*ES_S] = gelu(hi);
        upk(acc1, lo, hi); uc[(c0+2)*ES_S] = gelu(lo); uc[(c0+3)*ES_S] = gelu(hi);
        upk(acc2, lo, hi); uc[(c0+4)*ES_S] = gelu(lo); uc[(c0+5)*ES_S] = gelu(hi);
    }
    __syncthreads();

    // ---- P6b: m = v @ Wv2 + b2 ; scatter-add into g_agg[dst] ----
    {
        int g = tid >> 8;
        int t = tid & 255;
        int c0 = 6 * g;
        ull acc0 = 0ULL, acc1 = 0ULL, acc2 = 0ULL;
        const float* ub = us + t;
        const float* wb = sWv2 + c0;
        #pragma unroll 4
        for (int k = 0; k < HIDDEN; k++) {
            const ull* wr = (const ull*)(wb + k * HIDDEN);
            ull w0 = wr[0], w1 = wr[1], w2 = wr[2];
            float vv = ub[k * ES_S];
            ull v2 = pk(vv, vv);
            acc0 = fma2(v2, w0, acc0);
            acc1 = fma2(v2, w1, acc1);
            acc2 = fma2(v2, w2, acc2);
        }
        int d = didx[t];
        float* ag = g_agg + (size_t)d * HIDDEN + c0;
        float lo, hi;
        upk(acc0, lo, hi);
        atomicAdd(ag + 0, lo + svb2[c0+0]);
        atomicAdd(ag + 1, hi + svb2[c0+1]);
        upk(acc1, lo, hi);
        atomicAdd(ag + 2, lo + svb2[c0+2]);
        atomicAdd(ag + 3, hi + svb2[c0+3]);
        upk(acc2, lo, hi);
        atomicAdd(ag + 4, lo + svb2[c0+4]);
        atomicAdd(ag + 5, hi + svb2[c0+5]);
    }

    // ---- P7: write updated e tile back (skipped on last layer) ----
    if (store_e) {
        __syncthreads();
        for (int i = tid; i < EDGE_DIM * TE; i += ETHREADS) {
            int ee = i / EDGE_DIM, k = i - ee * EDGE_DIM;
            g_e[(size_t)(base + ee) * EDGE_DIM + k] = es[k * ES_S + ee];
        }
    }
}

// ---------------- node update: h = LN(h + agg / count) ----------------
__global__ void k_nodeup(const float* __restrict__ nvg, const float* __restrict__ nvb) {
    int n = blockIdx.x * blockDim.x + threadIdx.x;
    if (n >= N_NODES) return;
    float inv = 1.0f / fmaxf(g_cnt[n], 1.0f);
    float r[HIDDEN];
    float sum = 0.0f, sq = 0.0f;
    #pragma unroll
    for (int k = 0; k < HIDDEN; k += 4) {
        float4 hv = *(const float4*)(g_h + (size_t)n * HIDDEN + k);
        float4 av = *(const float4*)(g_agg + (size_t)n * HIDDEN + k);
        r[k]   = hv.x + av.x * inv; r[k+1] = hv.y + av.y * inv;
        r[k+2] = hv.z + av.z * inv; r[k+3] = hv.w + av.w * inv;
        sum += r[k] + r[k+1] + r[k+2] + r[k+3];
        sq  += r[k]*r[k] + r[k+1]*r[k+1] + r[k+2]*r[k+2] + r[k+3]*r[k+3];
    }
    float mean = sum * (1.0f / HIDDEN);
    float var  = fmaxf(sq * (1.0f / HIDDEN) - mean * mean, 0.0f);
    float rstd = rsqrtf(var + LN_EPS);
    #pragma unroll
    for (int k = 0; k < HIDDEN; k++) r[k] = (r[k] - mean) * rstd * nvg[k] + nvb[k];
    #pragma unroll
    for (int k = 0; k < HIDDEN; k += 4)
        *(float4*)(g_h + (size_t)n * HIDDEN + k) = make_float4(r[k], r[k+1], r[k+2], r[k+3]);
}

// ---------------- context head + final output ----------------
__global__ void __launch_bounds__(256) k_out(
    const float* __restrict__ ch_w1, const float* __restrict__ ch_b1,
    const float* __restrict__ ch_w2, const float* __restrict__ ch_b2,
    const float* __restrict__ mu, float* __restrict__ out)
{
    __shared__ float sw1[HIDDEN * HEAD_HIDDEN];
    __shared__ float sb1h[HEAD_HIDDEN];
    __shared__ float sw2[HEAD_HIDDEN];
    __shared__ float sb2h, smu;
    int tid = threadIdx.x;
    for (int i = tid; i < HIDDEN * HEAD_HIDDEN; i += 256) sw1[i] = ch_w1[i];
    if (tid < HEAD_HIDDEN) { sb1h[tid] = ch_b1[tid]; sw2[tid] = ch_w2[tid]; }
    if (tid == 0) { sb2h = ch_b2[0]; smu = mu[0]; }
    __syncthreads();
    int n = blockIdx.x * 256 + tid;
    if (n >= N_NODES) return;

    float h[HIDDEN];
    #pragma unroll
    for (int k = 0; k < HIDDEN; k += 4) {
        float4 v = *(const float4*)(g_h + (size_t)n * HIDDEN + k);
        h[k] = v.x; h[k+1] = v.y; h[k+2] = v.z; h[k+3] = v.w;
    }
    ull t[HEAD_HIDDEN / 2];
    #pragma unroll
    for (int j = 0; j < HEAD_HIDDEN / 2; j++) t[j] = pk(sb1h[2*j], sb1h[2*j+1]);
    #pragma unroll 4
    for (int k = 0; k < HIDDEN; k++) {
        ull hv = pk(h[k], h[k]);
        const ull* wr = (const ull*)(sw1 + k * HEAD_HIDDEN);
        #pragma unroll
        for (int j = 0; j < HEAD_HIDDEN / 2; j++) t[j] = fma2(hv, wr[j], t[j]);
    }
    float r = sb2h;
    #pragma unroll
    for (int j = 0; j < HEAD_HIDDEN / 2; j++) {
        float lo, hi; upk(t[j], lo, hi);
        r += gelu(lo) * sw2[2*j] + gelu(hi) * sw2[2*j+1];
    }
    out[n] = smu + g_intr[n] + r;
}

// ---------------- launch ----------------
extern "C" void kernel_launch(void* const* d_in, const int* in_sizes, int n_in,
                              void* d_out, int out_size) {
    (void)in_sizes; (void)n_in; (void)out_size;
    const float* x         = (const float*)d_in[0];
    const float* edge_attr = (const float*)d_in[1];
    const float* node_w    = (const float*)d_in[2];
    const float* node_b    = (const float*)d_in[3];
    const float* ih_w1     = (const float*)d_in[4];
    const float* ih_b1     = (const float*)d_in[5];
    const float* ih_w2     = (const float*)d_in[6];
    const float* ih_b2     = (const float*)d_in[7];
    const float* pe_w1     = (const float*)d_in[8];
    const float* pe_b1     = (const float*)d_in[9];
    const float* pe_w2     = (const float*)d_in[10];
    const float* pe_b2     = (const float*)d_in[11];
    const float* pv_w1     = (const float*)d_in[12];
    const float* pv_b1     = (const float*)d_in[13];
    const float* pv_w2     = (const float*)d_in[14];
    const float* pv_b2     = (const float*)d_in[15];
    const float* ne_g      = (const float*)d_in[16];
    const float* ne_b      = (const float*)d_in[17];
    const float* nv_g      = (const float*)d_in[18];
    const float* nv_b      = (const float*)d_in[19];
    const float* ch_w1     = (const float*)d_in[20];
    const float* ch_b1     = (const float*)d_in[21];
    const float* ch_w2     = (const float*)d_in[22];
    const float* ch_b2     = (const float*)d_in[23];
    const float* mu        = (const float*)d_in[24];
    const int*   eidx      = (const int*)d_in[25];
    const int* src = eidx;
    const int* dst = eidx + N_EDGES;
    float* out = (float*)d_out;

    cudaFuncSetAttribute(k_edge, cudaFuncAttributeMaxDynamicSharedMemorySize, EDGE_SMEM_BYTES);

    const int NB_N = (N_NODES + 255) / 256;
    const int NB_E = N_EDGES / 256;          // 3125, exact

    k_input<<<NB_N, 256>>>(x, node_w, node_b, ih_w1, ih_b1, ih_w2, ih_b2);
    k_count<<<NB_E, 256>>>(dst);

    for (int i = 0; i < DEPTH; i++) {
        const float* pe1 = pe_w1 + (size_t)i * 132 * EDGE_DIM;
        const float* pv1 = pv_w1 + (size_t)i * 132 * HIDDEN;
        k_nodeproj<<<NB_N, 256>>>(pe1, pv1);
        k_edge<<<NB_E, ETHREADS, EDGE_SMEM_BYTES>>>(
            (i == 0) ? edge_attr : (const float*)nullptr,
            src, dst,
            pe1 + 48 * EDGE_DIM,                 // We1: rows 48..131 of pe_w1[i]
            pe_b1 + (size_t)i * EDGE_DIM,
            pe_w2 + (size_t)i * EDGE_DIM * EDGE_DIM,
            pe_b2 + (size_t)i * EDGE_DIM,
            ne_g + (size_t)i * EDGE_DIM,
            ne_b + (size_t)i * EDGE_DIM,
            pv1 + 48 * HIDDEN,                   // Wv1: rows 48..131 of pv_w1[i]
            pv_b1 + (size_t)i * HIDDEN,
            pv_w2 + (size_t)i * HIDDEN * HIDDEN,
            pv_b2 + (size_t)i * HIDDEN,
            (i + 1 < DEPTH) ? 1 : 0);
        k_nodeup<<<NB_N, 256>>>(nv_g + (size_t)i * HIDDEN, nv_b + (size_t)i * HIDDEN);
    }

    k_out<<<NB_N, 256>>>(ch_w1, ch_b1, ch_w2, ch_b2, mu, out);
}